// round 13
// baseline (speedup 1.0000x reference)
#include <cuda_runtime.h>
#include <math.h>
#include <stdint.h>

#define BATCH 8192
#define PDIM  512
#define DM    256
#define DI    512
#define DTR   16
#define DS    16
#define ADIM  64
#define XDW   48

// ---- static scratch ----
__device__ float g_P[BATCH * PDIM];
__device__ float g_W[417792];            // tf32 weights: W_in | in_proj | x_proj
__device__ float g_WC[128 * DI];
__device__ float g_X[BATCH * DM];
__device__ float g_U2[BATCH * DI];
__device__ float g_G[BATCH * DI];
__device__ float g_XD[4 * BATCH * XDW];
__device__ float g_Y[BATCH * DI];
__device__ float g_HP[2 * BATCH * 128];

#define OFF_WIN   0
#define OFF_INPJ  131072
#define OFF_XPJ   393216
#define NW_TOTAL  417792
#define NP_TOTAL  (BATCH * PDIM)

__device__ __forceinline__ float cvt_tf32(float x) {
    uint32_t u;
    asm("cvt.rna.tf32.f32 %0, %1;" : "=r"(u) : "f"(x));
    return __uint_as_float(u);
}

__device__ __forceinline__ void mma_tf32(float* c, const uint32_t* a,
                                         uint32_t b0, uint32_t b1) {
    asm volatile(
        "mma.sync.aligned.m16n8k8.row.col.f32.tf32.tf32.f32 "
        "{%0,%1,%2,%3},{%4,%5,%6,%7},{%8,%9},{%0,%1,%2,%3};"
        : "+f"(c[0]), "+f"(c[1]), "+f"(c[2]), "+f"(c[3])
        : "r"(a[0]), "r"(a[1]), "r"(a[2]), "r"(a[3]), "r"(b0), "r"(b1));
}

__device__ __forceinline__ void cp16(uint32_t dst, const float* src, bool ok) {
    int sz = ok ? 16 : 0;
    asm volatile("cp.async.ca.shared.global [%0], [%1], 16, %2;"
                 :: "r"(dst), "l"(src), "r"(sz) : "memory");
}
#define CP_COMMIT() asm volatile("cp.async.commit_group;" ::: "memory")
#define CP_WAIT1()  asm volatile("cp.async.wait_group 1;" ::: "memory")

__device__ __forceinline__ float fast_sigmoid(float x) {
    return __fdividef(1.f, 1.f + __expf(-x));
}
__device__ __forceinline__ float fast_softplus(float x) {
    return (x > 15.f) ? x : __logf(1.f + __expf(x));
}
__device__ __forceinline__ float fast_tanh(float x) {
    float e = __expf(-2.f * fabsf(x));
    float t = __fdividef(1.f - e, 1.f + e);
    return copysignf(t, x);
}

__global__ void __launch_bounds__(256)
preround(const float* __restrict__ P,
         const float* __restrict__ w_in,  const float* __restrict__ in_proj,
         const float* __restrict__ x_proj,
         float* __restrict__ gP, float* __restrict__ gW) {
    int idx = blockIdx.x * 256 + threadIdx.x;
    if (idx < NP_TOTAL) { gP[idx] = cvt_tf32(P[idx]); return; }
    int j = idx - NP_TOTAL;
    if (j >= NW_TOTAL) return;
    float v;
    if      (j < OFF_INPJ) v = w_in[j - OFF_WIN];
    else if (j < OFF_XPJ)  v = in_proj[j - OFF_INPJ];
    else                   v = x_proj[j - OFF_XPJ];
    gW[j] = cvt_tf32(v);
}

__global__ void __launch_bounds__(256)
combine_heads(const float* __restrict__ mu_w, const float* __restrict__ ls_w,
              const float* __restrict__ out_proj, float* __restrict__ WC) {
    __shared__ float sM[64][65];
    __shared__ float sO[64][65];
    const int tid = threadIdx.x;
    const int bj = blockIdx.x * 64, bd = blockIdx.y * 64;
    const int ty = tid >> 4, tx = tid & 15;

    float acc[4][4];
#pragma unroll
    for (int i = 0; i < 4; i++)
#pragma unroll
        for (int j = 0; j < 4; j++) acc[i][j] = 0.f;

    for (int k0 = 0; k0 < DM; k0 += 64) {
        for (int i = tid; i < 64 * 16; i += 256) {
            int r = i >> 4, q = (i & 15) * 4;
            int jr = bj + r;
            const float* src = (jr < ADIM)
                ? (mu_w + (size_t)jr * DM + k0 + q)
                : (ls_w + (size_t)(jr - ADIM) * DM + k0 + q);
            float4 v = *(const float4*)src;
            sM[r][q] = v.x; sM[r][q + 1] = v.y; sM[r][q + 2] = v.z; sM[r][q + 3] = v.w;
        }
        for (int i = tid; i < 64 * 16; i += 256) {
            int r = i >> 4, q = (i & 15) * 4;
            float4 v = *(const float4*)(out_proj + (size_t)(k0 + r) * DI + bd + q);
            sO[r][q] = v.x; sO[r][q + 1] = v.y; sO[r][q + 2] = v.z; sO[r][q + 3] = v.w;
        }
        __syncthreads();
#pragma unroll 8
        for (int k = 0; k < 64; k++) {
            float a[4], b[4];
#pragma unroll
            for (int i = 0; i < 4; i++) { a[i] = sM[ty * 4 + i][k]; b[i] = sO[k][tx * 4 + i]; }
#pragma unroll
            for (int i = 0; i < 4; i++)
#pragma unroll
                for (int j = 0; j < 4; j++) acc[i][j] += a[i] * b[j];
        }
        __syncthreads();
    }
#pragma unroll
    for (int i = 0; i < 4; i++)
#pragma unroll
        for (int j = 0; j < 4; j++)
            WC[(size_t)(bj + ty * 4 + i) * DI + bd + tx * 4 + j] = cvt_tf32(acc[i][j]);
}

// ---------- narrow GEMM: BM=128 BN=64, warp 32x32 (proven) ----------
// EPI: 0 split-K partial, 1 X=cvt(v+bias)
template <int EPI>
__global__ void __launch_bounds__(256)
gemm_cp(const float* __restrict__ A, int lda,
        const float* __restrict__ W, int ldw, const float* __restrict__ bias,
        float* __restrict__ C, int ldc, int Nfull, int K, int pstride) {
    const int BM = 128, BN = 64, BK = 16, PAD = 20;
    __shared__ float As[3][BM][PAD];
    __shared__ float Ws[3][BN][PAD];

    const int tid  = threadIdx.x;
    const int lane = tid & 31, wid = tid >> 5;
    const int wm = (wid & 3) * 32, wn = (wid >> 2) * 32;
    const int g = lane >> 2, t = lane & 3;
    const int bm = blockIdx.x * BM;
    const int bn = blockIdx.y * BN;

    const int kz = blockIdx.z * K;
    const float* Ap = A + kz;
    const float* Wp = W + kz;
    float* Cz = (EPI == 0) ? (C + (size_t)blockIdx.z * pstride) : C;

    const int ar0 = tid >> 2;
    const int ak  = (tid & 3) * 4;
    const int nTiles = K / BK;

    const bool wok = (bn + ar0) < Nfull;
    const int wrow = wok ? (bn + ar0) : 0;

    uint32_t sA0 = (uint32_t)__cvta_generic_to_shared(&As[0][ar0][ak]);
    uint32_t sA1 = (uint32_t)__cvta_generic_to_shared(&As[0][ar0 + 64][ak]);
    uint32_t sW0 = (uint32_t)__cvta_generic_to_shared(&Ws[0][ar0][ak]);
    const uint32_t bufA = BM * PAD * 4;
    const uint32_t bufW = BN * PAD * 4;

    auto issue = [&](int kt, int b) {
        int k0 = kt * BK + ak;
        cp16(sA0 + b * bufA, Ap + (size_t)(bm + ar0) * lda + k0, true);
        cp16(sA1 + b * bufA, Ap + (size_t)(bm + ar0 + 64) * lda + k0, true);
        cp16(sW0 + b * bufW, Wp + (size_t)wrow * ldw + k0, wok);
    };

    float acc[2][4][4];
#pragma unroll
    for (int i = 0; i < 2; i++)
#pragma unroll
        for (int j = 0; j < 4; j++)
#pragma unroll
            for (int l = 0; l < 4; l++) acc[i][j][l] = 0.f;

    issue(0, 0); CP_COMMIT();
    issue(1, 1); CP_COMMIT();

    int cur = 0;
    for (int kt = 0; kt < nTiles; kt++) {
        CP_WAIT1();
        __syncthreads();
        if (kt + 2 < nTiles) issue(kt + 2, (kt + 2) % 3);
        CP_COMMIT();

#pragma unroll
        for (int ks = 0; ks < 2; ks++) {
            const int kb = ks * 8;
            uint32_t a[2][4];
#pragma unroll
            for (int mt = 0; mt < 2; mt++) {
                int row = wm + mt * 16 + g;
                a[mt][0] = __float_as_uint(As[cur][row][kb + t]);
                a[mt][1] = __float_as_uint(As[cur][row + 8][kb + t]);
                a[mt][2] = __float_as_uint(As[cur][row][kb + t + 4]);
                a[mt][3] = __float_as_uint(As[cur][row + 8][kb + t + 4]);
            }
#pragma unroll
            for (int nt = 0; nt < 4; nt++) {
                int nc = wn + nt * 8 + g;
                uint32_t b0 = __float_as_uint(Ws[cur][nc][kb + t]);
                uint32_t b1 = __float_as_uint(Ws[cur][nc][kb + t + 4]);
                mma_tf32(acc[0][nt], a[0], b0, b1);
                mma_tf32(acc[1][nt], a[1], b0, b1);
            }
        }
        cur = (cur + 1) % 3;
    }

#pragma unroll
    for (int mt = 0; mt < 2; mt++) {
#pragma unroll
        for (int nt = 0; nt < 4; nt++) {
#pragma unroll
            for (int ci = 0; ci < 4; ci++) {
                int row = bm + wm + mt * 16 + g + ((ci >= 2) ? 8 : 0);
                int col = bn + wn + nt * 8 + t * 2 + (ci & 1);
                float v = acc[mt][nt][ci];
                if (EPI == 0) {
                    if (col < Nfull) Cz[(size_t)row * ldc + col] = v;
                } else {
                    C[(size_t)row * ldc + col] = cvt_tf32(v + bias[col]);
                }
            }
        }
    }
}

// ---------- wide GEMM: BM=128 BN=128, warp 32x64 (1.5 LDS/MMA) ----------
// EPI: 0 split-K partial (heads), 2 in_proj fused (U2|G)
template <int EPI>
__global__ void __launch_bounds__(256)
gemm_w(const float* __restrict__ A, int lda,
       const float* __restrict__ W, int ldw,
       float* __restrict__ C, int ldc, int K, int pstride,
       const float* __restrict__ aux0, const float* __restrict__ aux1,
       float* __restrict__ aux2) {
    const int BM = 128, BN = 128, BK = 16, PAD = 20;
    __shared__ float As[3][BM][PAD];
    __shared__ float Ws[3][BN][PAD];

    const int tid  = threadIdx.x;
    const int lane = tid & 31, wid = tid >> 5;
    const int wm = (wid & 3) * 32;           // 4 warps over M
    const int wn = (wid >> 2) * 64;          // 2 warps over N
    const int g = lane >> 2, t = lane & 3;
    const int bm = blockIdx.x * BM;
    const int bn = blockIdx.y * BN;

    const int kz = blockIdx.z * K;
    const float* Ap = A + kz;
    const float* Wp = W + kz;
    float* Cz = (EPI == 0) ? (C + (size_t)blockIdx.z * pstride) : C;

    const int ar0 = tid >> 2;                // 0..63
    const int ak  = (tid & 3) * 4;
    const int nTiles = K / BK;

    uint32_t sA0 = (uint32_t)__cvta_generic_to_shared(&As[0][ar0][ak]);
    uint32_t sA1 = (uint32_t)__cvta_generic_to_shared(&As[0][ar0 + 64][ak]);
    uint32_t sW0 = (uint32_t)__cvta_generic_to_shared(&Ws[0][ar0][ak]);
    uint32_t sW1 = (uint32_t)__cvta_generic_to_shared(&Ws[0][ar0 + 64][ak]);
    const uint32_t bufA = BM * PAD * 4;
    const uint32_t bufW = BN * PAD * 4;

    auto issue = [&](int kt, int b) {
        int k0 = kt * BK + ak;
        cp16(sA0 + b * bufA, Ap + (size_t)(bm + ar0) * lda + k0, true);
        cp16(sA1 + b * bufA, Ap + (size_t)(bm + ar0 + 64) * lda + k0, true);
        cp16(sW0 + b * bufW, Wp + (size_t)(bn + ar0) * ldw + k0, true);
        cp16(sW1 + b * bufW, Wp + (size_t)(bn + ar0 + 64) * ldw + k0, true);
    };

    float acc[2][8][4];
#pragma unroll
    for (int i = 0; i < 2; i++)
#pragma unroll
        for (int j = 0; j < 8; j++)
#pragma unroll
            for (int l = 0; l < 4; l++) acc[i][j][l] = 0.f;

    issue(0, 0); CP_COMMIT();
    issue(1, 1); CP_COMMIT();

    int cur = 0;
    for (int kt = 0; kt < nTiles; kt++) {
        CP_WAIT1();
        __syncthreads();
        if (kt + 2 < nTiles) issue(kt + 2, (kt + 2) % 3);
        CP_COMMIT();

#pragma unroll
        for (int ks = 0; ks < 2; ks++) {
            const int kb = ks * 8;
            uint32_t a[2][4];
#pragma unroll
            for (int mt = 0; mt < 2; mt++) {
                int row = wm + mt * 16 + g;
                a[mt][0] = __float_as_uint(As[cur][row][kb + t]);
                a[mt][1] = __float_as_uint(As[cur][row + 8][kb + t]);
                a[mt][2] = __float_as_uint(As[cur][row][kb + t + 4]);
                a[mt][3] = __float_as_uint(As[cur][row + 8][kb + t + 4]);
            }
#pragma unroll
            for (int nt = 0; nt < 8; nt++) {
                int nc = wn + nt * 8 + g;
                uint32_t b0 = __float_as_uint(Ws[cur][nc][kb + t]);
                uint32_t b1 = __float_as_uint(Ws[cur][nc][kb + t + 4]);
                mma_tf32(acc[0][nt], a[0], b0, b1);
                mma_tf32(acc[1][nt], a[1], b0, b1);
            }
        }
        cur = (cur + 1) % 3;
    }

#pragma unroll
    for (int mt = 0; mt < 2; mt++) {
#pragma unroll
        for (int nt = 0; nt < 8; nt++) {
#pragma unroll
            for (int ci = 0; ci < 4; ci++) {
                int row = bm + wm + mt * 16 + g + ((ci >= 2) ? 8 : 0);
                int col = bn + wn + nt * 8 + t * 2 + (ci & 1);
                float v = acc[mt][nt][ci];
                if (EPI == 0) {
                    Cz[(size_t)row * ldc + col] = v;
                } else { // EPI == 2
                    if (col < DI) {
                        float u = v * aux0[col * 4 + 3] + aux1[col];
                        C[(size_t)row * DI + col] = cvt_tf32(u * fast_sigmoid(u)); // U2
                    } else {
                        aux2[(size_t)row * DI + (col - DI)] = v * fast_sigmoid(v); // G
                    }
                }
            }
        }
    }
}

__global__ void __launch_bounds__(256)
heads_epi(const float* __restrict__ HP, const float* __restrict__ mu_b,
          const float* __restrict__ ls_b, float* __restrict__ out_mu,
          float* __restrict__ out_ls) {
    int idx = (blockIdx.x * 256 + threadIdx.x) * 4;
    int row = idx >> 7, col = idx & 127;
    float4 p0 = *(const float4*)&HP[idx];
    float4 p1 = *(const float4*)&HP[(size_t)BATCH * 128 + idx];
    if (col < ADIM) {
        const float4 b = *(const float4*)&mu_b[col];
        float4 o;
        o.x = fast_tanh(p0.x + p1.x + b.x);
        o.y = fast_tanh(p0.y + p1.y + b.y);
        o.z = fast_tanh(p0.z + p1.z + b.z);
        o.w = fast_tanh(p0.w + p1.w + b.w);
        *(float4*)&out_mu[(size_t)row * ADIM + col] = o;
    } else {
        const float4 b = *(const float4*)&ls_b[col - ADIM];
        float4 o;
        o.x = fminf(fmaxf(p0.x + p1.x + b.x, -5.f), 2.f);
        o.y = fminf(fmaxf(p0.y + p1.y + b.y, -5.f), 2.f);
        o.z = fminf(fmaxf(p0.z + p1.z + b.z, -5.f), 2.f);
        o.w = fminf(fmaxf(p0.w + p1.w + b.w, -5.f), 2.f);
        *(float4*)&out_ls[(size_t)row * ADIM + (col - ADIM)] = o;
    }
}

#define RB2 8
__global__ void __launch_bounds__(512)
delta_ygate(const float* __restrict__ XD, const float* __restrict__ dtw,
            const float* __restrict__ dtb, const float* __restrict__ U2,
            const float* __restrict__ G, const float* __restrict__ Dskip,
            float* __restrict__ Y) {
    __shared__ float sXD[RB2][XDW];
    __shared__ float sbc[RB2];
    const int tid = threadIdx.x;
    const int r0 = blockIdx.x * RB2;

    if (tid < RB2 * 12) {
        int r = tid / 12, c4 = (tid % 12) * 4;
        size_t off = (size_t)(r0 + r) * XDW + c4;
        float4 s = *(const float4*)&XD[off];
#pragma unroll
        for (int p = 1; p < 4; p++) {
            float4 xp = *(const float4*)&XD[(size_t)p * BATCH * XDW + off];
            s.x += xp.x; s.y += xp.y; s.z += xp.z; s.w += xp.w;
        }
        *(float4*)&sXD[r][c4] = s;
    }
    __syncthreads();
    if (tid < RB2) {
        float s = 0.f;
#pragma unroll
        for (int k = 0; k < DS; k++) s += sXD[tid][DTR + k] * sXD[tid][DTR + DS + k];
        sbc[tid] = s;
    }

    float w[DTR];
#pragma unroll
    for (int i = 0; i < 4; i++)
        *(float4*)&w[i * 4] = *(const float4*)(dtw + (size_t)tid * DTR + i * 4);
    const float bv = dtb[tid];
    const float dv = Dskip[tid];
    __syncthreads();

    size_t base = (size_t)r0 * DI;
    float u = U2[base + tid];
    float gg = G[base + tid];
#pragma unroll
    for (int r = 0; r < RB2; r++) {
        float un, gn;
        if (r + 1 < RB2) {
            un = U2[base + DI + tid];
            gn = G[base + DI + tid];
        }
        float acc = bv;
#pragma unroll
        for (int k = 0; k < DTR; k++) acc += w[k] * sXD[r][k];
        float de = fast_softplus(acc);
        Y[base + tid] = cvt_tf32(u * (de * sbc[r] + dv) * gg);
        base += DI;
        u = un; gg = gn;
    }
}

extern "C" void kernel_launch(void* const* d_in, const int* in_sizes, int n_in,
                              void* d_out, int out_size) {
    const float* perception = (const float*)d_in[0];
    const float* W_in       = (const float*)d_in[1];
    const float* b_in       = (const float*)d_in[2];
    const float* mu_w       = (const float*)d_in[3];
    const float* mu_b       = (const float*)d_in[4];
    const float* ls_w       = (const float*)d_in[5];
    const float* ls_b       = (const float*)d_in[6];
    const float* in_proj_w  = (const float*)d_in[7];
    const float* conv_w     = (const float*)d_in[8];
    const float* conv_b     = (const float*)d_in[9];
    const float* x_proj_w   = (const float*)d_in[10];
    const float* dt_proj_w  = (const float*)d_in[11];
    const float* dt_proj_b  = (const float*)d_in[12];
    const float* Dskip      = (const float*)d_in[14];
    const float* out_proj_w = (const float*)d_in[15];

    float* out = (float*)d_out;

    float *P, *Wts, *WC, *X, *U2, *G, *XD, *Y, *HP;
    cudaGetSymbolAddress((void**)&P,   g_P);
    cudaGetSymbolAddress((void**)&Wts, g_W);
    cudaGetSymbolAddress((void**)&WC,  g_WC);
    cudaGetSymbolAddress((void**)&X,   g_X);
    cudaGetSymbolAddress((void**)&U2,  g_U2);
    cudaGetSymbolAddress((void**)&G,   g_G);
    cudaGetSymbolAddress((void**)&XD,  g_XD);
    cudaGetSymbolAddress((void**)&Y,   g_Y);
    cudaGetSymbolAddress((void**)&HP,  g_HP);

    const int MB = BATCH / 128;   // 64

    // 0) pre-round + fold heads through out_proj
    preround<<<(NP_TOTAL + NW_TOTAL + 255) / 256, 256>>>(
        perception, W_in, in_proj_w, x_proj_w, P, Wts);
    combine_heads<<<dim3(2, 8), 256>>>(mu_w, ls_w, out_proj_w, WC);

    // 1) X = cvt(perc @ W_in^T + b_in)       [8192,256] K=512  (narrow, grid 256)
    gemm_cp<1><<<dim3(MB, DM / 64), 256>>>(P, PDIM, Wts + OFF_WIN, PDIM, b_in,
                                           X, DM, DM, PDIM, 0);
    // 2) in_proj + silu-conv + silu(z)       [8192,1024] K=256 (wide, grid 512)
    gemm_w<2><<<dim3(MB, (2 * DI) / 128), 256>>>(X, DM, Wts + OFF_INPJ, DM,
                                                 U2, DI, DM, 0,
                                                 conv_w, conv_b, G);
    // 3) XD partials = U2 @ x_proj^T (split-K x4) [8192,48] (narrow)
    gemm_cp<0><<<dim3(MB, 1, 4), 256>>>(U2, DI, Wts + OFF_XPJ, DI, nullptr,
                                        XD, XDW, XDW, 128, BATCH * XDW);
    // 4) delta + bc + gate -> Y              [8192,512]
    delta_ygate<<<BATCH / RB2, 512>>>(XD, dt_proj_w, dt_proj_b, U2, G, Dskip, Y);
    // 5) head partials = Y @ WC^T (split-K x2) [8192,128] (wide, grid 128)
    gemm_w<0><<<dim3(MB, 1, 2), 256>>>(Y, DI, WC, DI,
                                       HP, 128, 256, BATCH * 128,
                                       nullptr, nullptr, nullptr);
    // 6) heads epilogue
    heads_epi<<<(BATCH * 128) / (256 * 4), 256>>>(HP, mu_b, ls_b,
                                                  out, out + (size_t)BATCH * ADIM);
    (void)in_sizes; (void)n_in; (void)out_size;
}

// round 14
// speedup vs baseline: 1.0639x; 1.0639x over previous
#include <cuda_runtime.h>
#include <math.h>
#include <stdint.h>

#define BATCH 8192
#define PDIM  512
#define DM    256
#define DI    512
#define DTR   16
#define DS    16
#define ADIM  64
#define XDW   48

// ---- static scratch ----
__device__ float g_P[BATCH * PDIM];
__device__ float g_W[417792];            // tf32 weights: W_in | in_proj | x_proj
__device__ float g_WC[128 * DI];
__device__ float g_X[BATCH * DM];
__device__ float g_U2[BATCH * DI];
__device__ float g_G[BATCH * DI];
__device__ float g_XD[4 * BATCH * XDW];
__device__ float g_Y[BATCH * DI];
__device__ float g_HP[2 * BATCH * 128];

#define OFF_WIN   0
#define OFF_INPJ  131072
#define OFF_XPJ   393216
#define NW_TOTAL  417792
#define NP_TOTAL  (BATCH * PDIM)

__device__ __forceinline__ float cvt_tf32(float x) {
    uint32_t u;
    asm("cvt.rna.tf32.f32 %0, %1;" : "=r"(u) : "f"(x));
    return __uint_as_float(u);
}

__device__ __forceinline__ void mma_tf32(float* c, const uint32_t* a,
                                         uint32_t b0, uint32_t b1) {
    asm volatile(
        "mma.sync.aligned.m16n8k8.row.col.f32.tf32.tf32.f32 "
        "{%0,%1,%2,%3},{%4,%5,%6,%7},{%8,%9},{%0,%1,%2,%3};"
        : "+f"(c[0]), "+f"(c[1]), "+f"(c[2]), "+f"(c[3])
        : "r"(a[0]), "r"(a[1]), "r"(a[2]), "r"(a[3]), "r"(b0), "r"(b1));
}

__device__ __forceinline__ void cp16(uint32_t dst, const float* src, bool ok) {
    int sz = ok ? 16 : 0;
    asm volatile("cp.async.ca.shared.global [%0], [%1], 16, %2;"
                 :: "r"(dst), "l"(src), "r"(sz) : "memory");
}
#define CP_COMMIT() asm volatile("cp.async.commit_group;" ::: "memory")
#define CP_WAIT1()  asm volatile("cp.async.wait_group 1;" ::: "memory")

__device__ __forceinline__ float fast_sigmoid(float x) {
    return __fdividef(1.f, 1.f + __expf(-x));
}
__device__ __forceinline__ float fast_softplus(float x) {
    return (x > 15.f) ? x : __logf(1.f + __expf(x));
}
__device__ __forceinline__ float fast_tanh(float x) {
    float e = __expf(-2.f * fabsf(x));
    float t = __fdividef(1.f - e, 1.f + e);
    return copysignf(t, x);
}

__global__ void __launch_bounds__(256)
preround(const float* __restrict__ P,
         const float* __restrict__ w_in,  const float* __restrict__ in_proj,
         const float* __restrict__ x_proj,
         float* __restrict__ gP, float* __restrict__ gW) {
    int idx = blockIdx.x * 256 + threadIdx.x;
    if (idx < NP_TOTAL) { gP[idx] = cvt_tf32(P[idx]); return; }
    int j = idx - NP_TOTAL;
    if (j >= NW_TOTAL) return;
    float v;
    if      (j < OFF_INPJ) v = w_in[j - OFF_WIN];
    else if (j < OFF_XPJ)  v = in_proj[j - OFF_INPJ];
    else                   v = x_proj[j - OFF_XPJ];
    gW[j] = cvt_tf32(v);
}

__global__ void __launch_bounds__(256)
combine_heads(const float* __restrict__ mu_w, const float* __restrict__ ls_w,
              const float* __restrict__ out_proj, float* __restrict__ WC) {
    __shared__ float sM[64][65];
    __shared__ float sO[64][65];
    const int tid = threadIdx.x;
    const int bj = blockIdx.x * 64, bd = blockIdx.y * 64;
    const int ty = tid >> 4, tx = tid & 15;

    float acc[4][4];
#pragma unroll
    for (int i = 0; i < 4; i++)
#pragma unroll
        for (int j = 0; j < 4; j++) acc[i][j] = 0.f;

    for (int k0 = 0; k0 < DM; k0 += 64) {
        for (int i = tid; i < 64 * 16; i += 256) {
            int r = i >> 4, q = (i & 15) * 4;
            int jr = bj + r;
            const float* src = (jr < ADIM)
                ? (mu_w + (size_t)jr * DM + k0 + q)
                : (ls_w + (size_t)(jr - ADIM) * DM + k0 + q);
            float4 v = *(const float4*)src;
            sM[r][q] = v.x; sM[r][q + 1] = v.y; sM[r][q + 2] = v.z; sM[r][q + 3] = v.w;
        }
        for (int i = tid; i < 64 * 16; i += 256) {
            int r = i >> 4, q = (i & 15) * 4;
            float4 v = *(const float4*)(out_proj + (size_t)(k0 + r) * DI + bd + q);
            sO[r][q] = v.x; sO[r][q + 1] = v.y; sO[r][q + 2] = v.z; sO[r][q + 3] = v.w;
        }
        __syncthreads();
#pragma unroll 8
        for (int k = 0; k < 64; k++) {
            float a[4], b[4];
#pragma unroll
            for (int i = 0; i < 4; i++) { a[i] = sM[ty * 4 + i][k]; b[i] = sO[k][tx * 4 + i]; }
#pragma unroll
            for (int i = 0; i < 4; i++)
#pragma unroll
                for (int j = 0; j < 4; j++) acc[i][j] += a[i] * b[j];
        }
        __syncthreads();
    }
#pragma unroll
    for (int i = 0; i < 4; i++)
#pragma unroll
        for (int j = 0; j < 4; j++)
            WC[(size_t)(bj + ty * 4 + i) * DI + bd + tx * 4 + j] = cvt_tf32(acc[i][j]);
}

// ---------- narrow GEMM: BM=128 BN=64 BK=16, warp 32x32 (proven) ----------
// EPI: 0 split-K partial, 1 X=cvt(v+bias)
template <int EPI>
__global__ void __launch_bounds__(256)
gemm_cp(const float* __restrict__ A, int lda,
        const float* __restrict__ W, int ldw, const float* __restrict__ bias,
        float* __restrict__ C, int ldc, int Nfull, int K, int pstride) {
    const int BM = 128, BN = 64, BK = 16, PAD = 20;
    __shared__ float As[3][BM][PAD];
    __shared__ float Ws[3][BN][PAD];

    const int tid  = threadIdx.x;
    const int lane = tid & 31, wid = tid >> 5;
    const int wm = (wid & 3) * 32, wn = (wid >> 2) * 32;
    const int g = lane >> 2, t = lane & 3;
    const int bm = blockIdx.x * BM;
    const int bn = blockIdx.y * BN;

    const int kz = blockIdx.z * K;
    const float* Ap = A + kz;
    const float* Wp = W + kz;
    float* Cz = (EPI == 0) ? (C + (size_t)blockIdx.z * pstride) : C;

    const int ar0 = tid >> 2;
    const int ak  = (tid & 3) * 4;
    const int nTiles = K / BK;

    const bool wok = (bn + ar0) < Nfull;
    const int wrow = wok ? (bn + ar0) : 0;

    uint32_t sA0 = (uint32_t)__cvta_generic_to_shared(&As[0][ar0][ak]);
    uint32_t sA1 = (uint32_t)__cvta_generic_to_shared(&As[0][ar0 + 64][ak]);
    uint32_t sW0 = (uint32_t)__cvta_generic_to_shared(&Ws[0][ar0][ak]);
    const uint32_t bufA = BM * PAD * 4;
    const uint32_t bufW = BN * PAD * 4;

    auto issue = [&](int kt, int b) {
        int k0 = kt * BK + ak;
        cp16(sA0 + b * bufA, Ap + (size_t)(bm + ar0) * lda + k0, true);
        cp16(sA1 + b * bufA, Ap + (size_t)(bm + ar0 + 64) * lda + k0, true);
        cp16(sW0 + b * bufW, Wp + (size_t)wrow * ldw + k0, wok);
    };

    float acc[2][4][4];
#pragma unroll
    for (int i = 0; i < 2; i++)
#pragma unroll
        for (int j = 0; j < 4; j++)
#pragma unroll
            for (int l = 0; l < 4; l++) acc[i][j][l] = 0.f;

    issue(0, 0); CP_COMMIT();
    issue(1, 1); CP_COMMIT();

    int cur = 0;
    for (int kt = 0; kt < nTiles; kt++) {
        CP_WAIT1();
        __syncthreads();
        if (kt + 2 < nTiles) issue(kt + 2, (kt + 2) % 3);
        CP_COMMIT();

#pragma unroll
        for (int ks = 0; ks < 2; ks++) {
            const int kb = ks * 8;
            uint32_t a[2][4];
#pragma unroll
            for (int mt = 0; mt < 2; mt++) {
                int row = wm + mt * 16 + g;
                a[mt][0] = __float_as_uint(As[cur][row][kb + t]);
                a[mt][1] = __float_as_uint(As[cur][row + 8][kb + t]);
                a[mt][2] = __float_as_uint(As[cur][row][kb + t + 4]);
                a[mt][3] = __float_as_uint(As[cur][row + 8][kb + t + 4]);
            }
#pragma unroll
            for (int nt = 0; nt < 4; nt++) {
                int nc = wn + nt * 8 + g;
                uint32_t b0 = __float_as_uint(Ws[cur][nc][kb + t]);
                uint32_t b1 = __float_as_uint(Ws[cur][nc][kb + t + 4]);
                mma_tf32(acc[0][nt], a[0], b0, b1);
                mma_tf32(acc[1][nt], a[1], b0, b1);
            }
        }
        cur = (cur + 1) % 3;
    }

#pragma unroll
    for (int mt = 0; mt < 2; mt++) {
#pragma unroll
        for (int nt = 0; nt < 4; nt++) {
#pragma unroll
            for (int ci = 0; ci < 4; ci++) {
                int row = bm + wm + mt * 16 + g + ((ci >= 2) ? 8 : 0);
                int col = bn + wn + nt * 8 + t * 2 + (ci & 1);
                float v = acc[mt][nt][ci];
                if (EPI == 0) {
                    if (col < Nfull) Cz[(size_t)row * ldc + col] = v;
                } else {
                    C[(size_t)row * ldc + col] = cvt_tf32(v + bias[col]);
                }
            }
        }
    }
}

// ---------- BK=32 GEMM for stage 2: BM=128 BN=64, warp 32x32, 3-stage ------
// Half the barrier rate of BK=16; 64 MMAs between syncs. Dynamic smem 83KB.
#define B32_PAD   36
#define B32_SMEM  (3 * (128 + 64) * B32_PAD * 4)
__global__ void __launch_bounds__(256)
gemm_b32_inproj(const float* __restrict__ A, int lda,
                const float* __restrict__ W, int ldw,
                float* __restrict__ U2out, int K,
                const float* __restrict__ convw, const float* __restrict__ convb,
                float* __restrict__ Gout) {
    const int BM = 128, BN = 64, PAD = B32_PAD;
    extern __shared__ float sm[];
    float* smA = sm;                     // [3*BM][PAD]
    float* smW = sm + 3 * BM * PAD;      // [3*BN][PAD]

    const int tid  = threadIdx.x;
    const int lane = tid & 31, wid = tid >> 5;
    const int wm = (wid & 3) * 32, wn = (wid >> 2) * 32;
    const int g = lane >> 2, t = lane & 3;
    const int bm = blockIdx.x * BM;
    const int bn = blockIdx.y * BN;

    const int ar0 = tid >> 2;            // 0..63
    const int ak  = (tid & 3) * 4;       // 0,4,8,12
    const int nT = K >> 5;               // BK = 32

    uint32_t aB = (uint32_t)__cvta_generic_to_shared(smA);
    uint32_t wB = (uint32_t)__cvta_generic_to_shared(smW);

    auto issue = [&](int kt, int b) {
        int k0 = kt * 32;
        const float* Ar0 = A + (size_t)(bm + ar0) * lda + k0;
        const float* Ar1 = A + (size_t)(bm + ar0 + 64) * lda + k0;
        const float* Wr  = W + (size_t)(bn + ar0) * ldw + k0;
        uint32_t a0 = aB + (uint32_t)(b * BM + ar0) * PAD * 4;
        uint32_t a1 = aB + (uint32_t)(b * BM + ar0 + 64) * PAD * 4;
        uint32_t w0 = wB + (uint32_t)(b * BN + ar0) * PAD * 4;
        cp16(a0 + ak * 4,        Ar0 + ak,      true);
        cp16(a0 + (ak + 16) * 4, Ar0 + ak + 16, true);
        cp16(a1 + ak * 4,        Ar1 + ak,      true);
        cp16(a1 + (ak + 16) * 4, Ar1 + ak + 16, true);
        cp16(w0 + ak * 4,        Wr + ak,       true);
        cp16(w0 + (ak + 16) * 4, Wr + ak + 16,  true);
    };

    float acc[2][4][4];
#pragma unroll
    for (int i = 0; i < 2; i++)
#pragma unroll
        for (int j = 0; j < 4; j++)
#pragma unroll
            for (int l = 0; l < 4; l++) acc[i][j][l] = 0.f;

    issue(0, 0); CP_COMMIT();
    issue(1, 1); CP_COMMIT();

    int cur = 0;
    for (int kt = 0; kt < nT; kt++) {
        CP_WAIT1();
        __syncthreads();
        if (kt + 2 < nT) issue(kt + 2, (kt + 2) % 3);
        CP_COMMIT();

        const float* As = smA + (size_t)cur * BM * PAD;
        const float* Ws = smW + (size_t)cur * BN * PAD;
#pragma unroll
        for (int ks = 0; ks < 4; ks++) {
            const int kb = ks * 8;
            uint32_t a[2][4];
#pragma unroll
            for (int mt = 0; mt < 2; mt++) {
                int row = wm + mt * 16 + g;
                a[mt][0] = __float_as_uint(As[row * PAD + kb + t]);
                a[mt][1] = __float_as_uint(As[(row + 8) * PAD + kb + t]);
                a[mt][2] = __float_as_uint(As[row * PAD + kb + t + 4]);
                a[mt][3] = __float_as_uint(As[(row + 8) * PAD + kb + t + 4]);
            }
#pragma unroll
            for (int nt = 0; nt < 4; nt++) {
                int nc = wn + nt * 8 + g;
                uint32_t b0 = __float_as_uint(Ws[nc * PAD + kb + t]);
                uint32_t b1 = __float_as_uint(Ws[nc * PAD + kb + t + 4]);
                mma_tf32(acc[0][nt], a[0], b0, b1);
                mma_tf32(acc[1][nt], a[1], b0, b1);
            }
        }
        cur = (cur + 1) % 3;
    }

#pragma unroll
    for (int mt = 0; mt < 2; mt++) {
#pragma unroll
        for (int nt = 0; nt < 4; nt++) {
#pragma unroll
            for (int ci = 0; ci < 4; ci++) {
                int row = bm + wm + mt * 16 + g + ((ci >= 2) ? 8 : 0);
                int col = bn + wn + nt * 8 + t * 2 + (ci & 1);
                float v = acc[mt][nt][ci];
                if (col < DI) {
                    float u = v * convw[col * 4 + 3] + convb[col];
                    U2out[(size_t)row * DI + col] = cvt_tf32(u * fast_sigmoid(u));
                } else {
                    Gout[(size_t)row * DI + (col - DI)] = v * fast_sigmoid(v);
                }
            }
        }
    }
}

__global__ void __launch_bounds__(256)
heads_epi(const float* __restrict__ HP, const float* __restrict__ mu_b,
          const float* __restrict__ ls_b, float* __restrict__ out_mu,
          float* __restrict__ out_ls) {
    int idx = (blockIdx.x * 256 + threadIdx.x) * 4;
    int row = idx >> 7, col = idx & 127;
    float4 p0 = *(const float4*)&HP[idx];
    float4 p1 = *(const float4*)&HP[(size_t)BATCH * 128 + idx];
    if (col < ADIM) {
        const float4 b = *(const float4*)&mu_b[col];
        float4 o;
        o.x = fast_tanh(p0.x + p1.x + b.x);
        o.y = fast_tanh(p0.y + p1.y + b.y);
        o.z = fast_tanh(p0.z + p1.z + b.z);
        o.w = fast_tanh(p0.w + p1.w + b.w);
        *(float4*)&out_mu[(size_t)row * ADIM + col] = o;
    } else {
        const float4 b = *(const float4*)&ls_b[col - ADIM];
        float4 o;
        o.x = fminf(fmaxf(p0.x + p1.x + b.x, -5.f), 2.f);
        o.y = fminf(fmaxf(p0.y + p1.y + b.y, -5.f), 2.f);
        o.z = fminf(fmaxf(p0.z + p1.z + b.z, -5.f), 2.f);
        o.w = fminf(fmaxf(p0.w + p1.w + b.w, -5.f), 2.f);
        *(float4*)&out_ls[(size_t)row * ADIM + (col - ADIM)] = o;
    }
}

#define RB2 8
__global__ void __launch_bounds__(512)
delta_ygate(const float* __restrict__ XD, const float* __restrict__ dtw,
            const float* __restrict__ dtb, const float* __restrict__ U2,
            const float* __restrict__ G, const float* __restrict__ Dskip,
            float* __restrict__ Y) {
    __shared__ float sXD[RB2][XDW];
    __shared__ float sbc[RB2];
    const int tid = threadIdx.x;
    const int r0 = blockIdx.x * RB2;

    if (tid < RB2 * 12) {
        int r = tid / 12, c4 = (tid % 12) * 4;
        size_t off = (size_t)(r0 + r) * XDW + c4;
        float4 s = *(const float4*)&XD[off];
#pragma unroll
        for (int p = 1; p < 4; p++) {
            float4 xp = *(const float4*)&XD[(size_t)p * BATCH * XDW + off];
            s.x += xp.x; s.y += xp.y; s.z += xp.z; s.w += xp.w;
        }
        *(float4*)&sXD[r][c4] = s;
    }
    __syncthreads();
    if (tid < RB2) {
        float s = 0.f;
#pragma unroll
        for (int k = 0; k < DS; k++) s += sXD[tid][DTR + k] * sXD[tid][DTR + DS + k];
        sbc[tid] = s;
    }

    float w[DTR];
#pragma unroll
    for (int i = 0; i < 4; i++)
        *(float4*)&w[i * 4] = *(const float4*)(dtw + (size_t)tid * DTR + i * 4);
    const float bv = dtb[tid];
    const float dv = Dskip[tid];
    __syncthreads();

    size_t base = (size_t)r0 * DI;
    float u = U2[base + tid];
    float gg = G[base + tid];
#pragma unroll
    for (int r = 0; r < RB2; r++) {
        float un, gn;
        if (r + 1 < RB2) {
            un = U2[base + DI + tid];
            gn = G[base + DI + tid];
        }
        float acc = bv;
#pragma unroll
        for (int k = 0; k < DTR; k++) acc += w[k] * sXD[r][k];
        float de = fast_softplus(acc);
        Y[base + tid] = cvt_tf32(u * (de * sbc[r] + dv) * gg);
        base += DI;
        u = un; gg = gn;
    }
}

extern "C" void kernel_launch(void* const* d_in, const int* in_sizes, int n_in,
                              void* d_out, int out_size) {
    const float* perception = (const float*)d_in[0];
    const float* W_in       = (const float*)d_in[1];
    const float* b_in       = (const float*)d_in[2];
    const float* mu_w       = (const float*)d_in[3];
    const float* mu_b       = (const float*)d_in[4];
    const float* ls_w       = (const float*)d_in[5];
    const float* ls_b       = (const float*)d_in[6];
    const float* in_proj_w  = (const float*)d_in[7];
    const float* conv_w     = (const float*)d_in[8];
    const float* conv_b     = (const float*)d_in[9];
    const float* x_proj_w   = (const float*)d_in[10];
    const float* dt_proj_w  = (const float*)d_in[11];
    const float* dt_proj_b  = (const float*)d_in[12];
    const float* Dskip      = (const float*)d_in[14];
    const float* out_proj_w = (const float*)d_in[15];

    float* out = (float*)d_out;

    float *P, *Wts, *WC, *X, *U2, *G, *XD, *Y, *HP;
    cudaGetSymbolAddress((void**)&P,   g_P);
    cudaGetSymbolAddress((void**)&Wts, g_W);
    cudaGetSymbolAddress((void**)&WC,  g_WC);
    cudaGetSymbolAddress((void**)&X,   g_X);
    cudaGetSymbolAddress((void**)&U2,  g_U2);
    cudaGetSymbolAddress((void**)&G,   g_G);
    cudaGetSymbolAddress((void**)&XD,  g_XD);
    cudaGetSymbolAddress((void**)&Y,   g_Y);
    cudaGetSymbolAddress((void**)&HP,  g_HP);

    // allow 83KB dynamic smem for the BK=32 kernel (idempotent host call)
    cudaFuncSetAttribute(gemm_b32_inproj,
                         cudaFuncAttributeMaxDynamicSharedMemorySize, B32_SMEM);

    const int MB = BATCH / 128;   // 64

    // 0) pre-round + fold heads through out_proj
    preround<<<(NP_TOTAL + NW_TOTAL + 255) / 256, 256>>>(
        perception, W_in, in_proj_w, x_proj_w, P, Wts);
    combine_heads<<<dim3(2, 8), 256>>>(mu_w, ls_w, out_proj_w, WC);

    // 1) X = cvt(perc @ W_in^T + b_in)       [8192,256] K=512  (narrow BK16)
    gemm_cp<1><<<dim3(MB, DM / 64), 256>>>(P, PDIM, Wts + OFF_WIN, PDIM, b_in,
                                           X, DM, DM, PDIM, 0);
    // 2) in_proj + silu-conv + silu(z)       [8192,1024] K=256  (BK32, grid 1024)
    gemm_b32_inproj<<<dim3(MB, (2 * DI) / 64), 256, B32_SMEM>>>(
        X, DM, Wts + OFF_INPJ, DM, U2, DM, conv_w, conv_b, G);
    // 3) XD partials = U2 @ x_proj^T (split-K x4) [8192,48] (narrow BK16)
    gemm_cp<0><<<dim3(MB, 1, 4), 256>>>(U2, DI, Wts + OFF_XPJ, DI, nullptr,
                                        XD, XDW, XDW, 128, BATCH * XDW);
    // 4) delta + bc + gate -> Y              [8192,512]
    delta_ygate<<<BATCH / RB2, 512>>>(XD, dt_proj_w, dt_proj_b, U2, G, Dskip, Y);
    // 5) head partials = Y @ WC^T (split-K x2) [8192,128] (narrow BK16)
    gemm_cp<0><<<dim3(MB, 2, 2), 256>>>(Y, DI, WC, DI, nullptr,
                                        HP, 128, 128, 256, BATCH * 128);
    // 6) heads epilogue
    heads_epi<<<(BATCH * 128) / (256 * 4), 256>>>(HP, mu_b, ls_b,
                                                  out, out + (size_t)BATCH * ADIM);
    (void)in_sizes; (void)n_in; (void)out_size;
}